// round 9
// baseline (speedup 1.0000x reference)
#include <cuda_runtime.h>
#include <cstdint>

// ---------------- problem constants ----------------
#define E_EXPERTS 128
#define MFEAT     2048            // GEMM K
#define NFEAT     1408            // GEMM N
#define S_TOK     16384
#define TILE_M    128
#define TILE_N    128
#define KC        32              // K floats per chunk
#define NCHUNK    (MFEAT / KC)    // 64
#define NTN       (NFEAT / TILE_N)// 11
#define MAXTILES  256             // sum ceil(b_e/128) <= 128 + 16384/128 = 256
#define GRID_CTAS (MAXTILES * NTN)

#define A_STRIDE  36              // floats per A smem row (32 + 4 pad) -> conflict-free
#define B_STRIDE  132             // floats per B smem row (128 + 4 pad) -> conflict-free
#define A_FLOATS  (TILE_M * A_STRIDE)   // 4608
#define B_FLOATS  (KC * B_STRIDE)       // 4224
#define STAGE_FLOATS (A_FLOATS + B_FLOATS)  // 8832
#define SMEM_BYTES   (2 * STAGE_FLOATS * 4) // 70656

// ---------------- scheduler output ----------------
__device__ int g_ntiles;
__device__ int g_te[MAXTILES];
__device__ int g_tr0[MAXTILES];
__device__ int g_tlim[MAXTILES];

// ---------------- helpers ----------------
__device__ __forceinline__ uint32_t f2tf32(float f) {
    uint32_t r;
    asm("cvt.rna.tf32.f32 %0, %1;" : "=r"(r) : "f"(f));
    return r;
}

__device__ __forceinline__ void mma_m16n8k8(float* d,
        uint32_t a0, uint32_t a1, uint32_t a2, uint32_t a3,
        uint32_t b0, uint32_t b1) {
    asm volatile(
        "mma.sync.aligned.m16n8k8.row.col.f32.tf32.tf32.f32 "
        "{%0,%1,%2,%3}, {%4,%5,%6,%7}, {%8,%9}, {%0,%1,%2,%3};"
        : "+f"(d[0]), "+f"(d[1]), "+f"(d[2]), "+f"(d[3])
        : "r"(a0), "r"(a1), "r"(a2), "r"(a3), "r"(b0), "r"(b1));
}

// ---------------- scheduler ----------------
__global__ void sched_kernel(const int* __restrict__ bs) {
    if (threadIdx.x == 0) {
        int off = 0, nt = 0;
        for (int e = 0; e < E_EXPERTS; e++) {
            int b = bs[e];
            for (int r = 0; r < b; r += TILE_M) {
                g_te[nt] = e; g_tr0[nt] = off + r; g_tlim[nt] = off + b; nt++;
            }
            off += b;
        }
        g_ntiles = nt;
    }
}

// ---------------- gmem -> regs loader ----------------
// A: 128 rows x 32 k = 1024 float4 tasks; thread covers (m = tid>>3 + 16j, f4 = tid&7)
//    -> per-warp: 4 rows x 8 lanes x 16B contiguous (coalesced)
// B: 32 k-rows x 128 n = 1024 float4 tasks; thread covers (k = tid>>5 + 4j, n4 = tid&31)
//    -> per-warp: one full 512B row (coalesced)
__device__ __forceinline__ void ldg_chunk(int c, float4 (&la)[8], float4 (&lb)[8],
        const float* __restrict__ x, const float* __restrict__ wb,
        int r0, int tid) {
    int la_f  = tid & 7;
    int la_m0 = tid >> 3;
    int lb_n4 = tid & 31;
    int lb_k0 = tid >> 5;
#pragma unroll
    for (int j = 0; j < 8; j++) {
        int m = la_m0 + 16 * j;
        int gr = r0 + m;
        if (gr < S_TOK)
            la[j] = *(const float4*)(x + (size_t)gr * MFEAT + c * KC + la_f * 4);
        else
            la[j] = make_float4(0.f, 0.f, 0.f, 0.f);
    }
#pragma unroll
    for (int j = 0; j < 8; j++) {
        int k = lb_k0 + 4 * j;
        lb[j] = *(const float4*)(wb + (size_t)(c * KC + k) * NFEAT + lb_n4 * 4);
    }
}

// ---------------- regs -> smem (with rna tf32 conversion) ----------------
// A STS128 banks: addr16 = 9m + f  -> conflict-free per phase
// B STS128 banks: addr16 = 33k + n -> conflict-free per phase
__device__ __forceinline__ void sts_chunk(float* st, const float4 (&la)[8], const float4 (&lb)[8],
        int tid) {
    float* As = st;
    float* Bs = st + A_FLOATS;
    int la_f  = tid & 7;
    int la_m0 = tid >> 3;
    int lb_n4 = tid & 31;
    int lb_k0 = tid >> 5;
#pragma unroll
    for (int j = 0; j < 8; j++) {
        int m = la_m0 + 16 * j;
        uint4 v;
        v.x = f2tf32(la[j].x); v.y = f2tf32(la[j].y);
        v.z = f2tf32(la[j].z); v.w = f2tf32(la[j].w);
        *(uint4*)(As + m * A_STRIDE + la_f * 4) = v;
    }
#pragma unroll
    for (int j = 0; j < 8; j++) {
        int k = lb_k0 + 4 * j;
        uint4 v;
        v.x = f2tf32(lb[j].x); v.y = f2tf32(lb[j].y);
        v.z = f2tf32(lb[j].z); v.w = f2tf32(lb[j].w);
        *(uint4*)(Bs + k * B_STRIDE + lb_n4 * 4) = v;
    }
}

// ---------------- main grouped-GEMM kernel ----------------
// 128 threads, 4 warps in 2x2 grid, warp tile 64x64, double-buffered K=32 chunks.
__global__ __launch_bounds__(128, 2)
void gg_kernel(const float* __restrict__ x, const float* __restrict__ w, float* __restrict__ out) {
    int job = blockIdx.x;
    int tm = job / NTN;
    if (tm >= g_ntiles) return;
    int n0   = (job - tm * NTN) * TILE_N;
    int e    = g_te[tm];
    int r0   = g_tr0[tm];
    int rlim = g_tlim[tm];
    const float* wb = w + (size_t)e * ((size_t)MFEAT * NFEAT) + n0;

    extern __shared__ __align__(16) float smem[];
    int tid  = threadIdx.x;
    int lane = tid & 31;
    int wid  = tid >> 5;
    int m0w  = (wid & 1) * 64;   // warp m-offset
    int n0w  = (wid >> 1) * 64;  // warp n-offset

    float acc[4][8][4];
#pragma unroll
    for (int i = 0; i < 4; i++)
#pragma unroll
        for (int j = 0; j < 8; j++)
#pragma unroll
            for (int q = 0; q < 4; q++) acc[i][j][q] = 0.f;

    float4 la[8], lb[8];

    // preload chunk 0
    ldg_chunk(0, la, lb, x, wb, r0, tid);
    sts_chunk(smem, la, lb, tid);
    __syncthreads();

    int lr = lane >> 2;   // 0..7 (row-within-frag / col-quad)
    int lc = lane & 3;    // 0..3 (k-within-step / col-pair)

    for (int c = 0; c < NCHUNK; c++) {
        const float* st = smem + (size_t)(c & 1) * STAGE_FLOATS;
        const uint32_t* As = (const uint32_t*)st;
        const uint32_t* Bs = (const uint32_t*)(st + A_FLOATS);

        if (c + 1 < NCHUNK)
            ldg_chunk(c + 1, la, lb, x, wb, r0, tid);  // issued early; consumed at STS below

#pragma unroll
        for (int s = 0; s < 4; s++) {   // 4 k-steps of 8 within the 32-chunk
            uint32_t af[4][4];
            uint32_t bf[8][2];
#pragma unroll
            for (int mf = 0; mf < 4; mf++) {
                const uint32_t* p = As + (size_t)(m0w + mf * 16 + lr) * A_STRIDE + s * 8 + lc;
                af[mf][0] = p[0];                   // a0: (row, k)
                af[mf][2] = p[4];                   // a2: (row, k+4)
                af[mf][1] = p[8 * A_STRIDE];        // a1: (row+8, k)
                af[mf][3] = p[8 * A_STRIDE + 4];    // a3: (row+8, k+4)
            }
#pragma unroll
            for (int nf = 0; nf < 8; nf++) {
                const uint32_t* p = Bs + (size_t)(s * 8 + lc) * B_STRIDE + n0w + nf * 8 + lr;
                bf[nf][0] = p[0];                   // b0: (k,   n)
                bf[nf][1] = p[4 * B_STRIDE];        // b1: (k+4, n)
            }
#pragma unroll
            for (int mf = 0; mf < 4; mf++)
#pragma unroll
                for (int nf = 0; nf < 8; nf++)
                    mma_m16n8k8(acc[mf][nf],
                                af[mf][0], af[mf][1], af[mf][2], af[mf][3],
                                bf[nf][0], bf[nf][1]);
        }

        if (c + 1 < NCHUNK)
            sts_chunk(smem + (size_t)((c + 1) & 1) * STAGE_FLOATS, la, lb, tid);
        __syncthreads();
    }

    // ---------------- epilogue ----------------
    // d0/d1: (row,       2*lc), (row,       2*lc+1)
    // d2/d3: (row+8,     2*lc), (row+8,     2*lc+1)
#pragma unroll
    for (int mf = 0; mf < 4; mf++) {
        int r_lo = r0 + m0w + mf * 16 + lr;
#pragma unroll
        for (int h = 0; h < 2; h++) {
            int gr = r_lo + h * 8;
            if (gr < rlim) {
                float* orow = out + (size_t)gr * NFEAT + n0 + n0w + 2 * lc;
#pragma unroll
                for (int nf = 0; nf < 8; nf++) {
                    float2 v;
                    v.x = acc[mf][nf][h * 2 + 0];
                    v.y = acc[mf][nf][h * 2 + 1];
                    *(float2*)(orow + nf * 8) = v;
                }
            }
        }
    }
}

// ---------------- launch ----------------
extern "C" void kernel_launch(void* const* d_in, const int* in_sizes, int n_in,
                              void* d_out, int out_size) {
    const float* x  = (const float*)d_in[0];
    const float* w  = (const float*)d_in[1];
    const int*   bs = (const int*)d_in[2];
    float* out = (float*)d_out;

    cudaFuncSetAttribute(gg_kernel, cudaFuncAttributeMaxDynamicSharedMemorySize, SMEM_BYTES);
    sched_kernel<<<1, 32>>>(bs);
    gg_kernel<<<GRID_CTAS, 128, SMEM_BYTES>>>(x, w, out);
}

// round 11
// speedup vs baseline: 1.1985x; 1.1985x over previous
#include <cuda_runtime.h>
#include <cstdint>

// ---------------- problem constants ----------------
#define E_EXPERTS 128
#define MFEAT     2048            // GEMM K
#define NFEAT     1408            // GEMM N
#define S_TOK     16384
#define TILE_M    128
#define TILE_N    128
#define KC        32              // K floats per chunk
#define NCHUNK    (MFEAT / KC)    // 64
#define NTN       (NFEAT / TILE_N)// 11
#define MAXTILES  256
#define GRID_CTAS (MAXTILES * NTN)
#define STAGES    3

#define A_STRIDE  36              // floats/row: 32 data + 4 pad; 144B rows (16B-mult)
#define B_STRIDE  136             // floats/row: 128 data + 8 pad; bank=(8lc+lr) conflict-free
#define A_FLOATS  (TILE_M * A_STRIDE)       // 4608
#define B_FLOATS  (KC * B_STRIDE)           // 4352
#define STAGE_FLOATS (A_FLOATS + B_FLOATS)  // 8960
#define STAGE_BYTES  (STAGE_FLOATS * 4)     // 35840
#define SMEM_DYN     (STAGES * STAGE_BYTES) // 107520 -> 2 CTAs/SM fits 228KB

// ---------------- scheduler output ----------------
__device__ int g_ntiles;
__device__ int g_te[MAXTILES];
__device__ int g_tr0[MAXTILES];
__device__ int g_tlim[MAXTILES];

// ---------------- helpers ----------------
__device__ __forceinline__ uint32_t smem_u32(const void* p) {
    uint32_t a;
    asm("{ .reg .u64 t; cvta.to.shared.u64 t, %1; cvt.u32.u64 %0, t; }" : "=r"(a) : "l"(p));
    return a;
}

// cp.async 16B with zero-fill when pred==0 (src-size operand form)
__device__ __forceinline__ void cp16(uint32_t dst, const void* src, int pred) {
    asm volatile(
        "{\n\t.reg .pred p;\n\t.reg .b32 s;\n\t"
        "setp.ne.u32 p, %2, 0;\n\t"
        "selp.b32 s, 16, 0, p;\n\t"
        "cp.async.cg.shared.global [%0], [%1], 16, s;\n\t}"
        :: "r"(dst), "l"(src), "r"(pred));
}
#define CP_COMMIT() asm volatile("cp.async.commit_group;" ::: "memory")
#define CP_WAIT2()  asm volatile("cp.async.wait_group 2;" ::: "memory")

__device__ __forceinline__ void ldsm_x4(uint32_t& r0, uint32_t& r1, uint32_t& r2, uint32_t& r3,
                                        uint32_t addr) {
    asm volatile("ldmatrix.sync.aligned.m8n8.x4.shared.b16 {%0,%1,%2,%3}, [%4];"
                 : "=r"(r0), "=r"(r1), "=r"(r2), "=r"(r3) : "r"(addr));
}

__device__ __forceinline__ void mma_m16n8k8(float* d,
        uint32_t a0, uint32_t a1, uint32_t a2, uint32_t a3,
        uint32_t b0, uint32_t b1) {
    asm volatile(
        "mma.sync.aligned.m16n8k8.row.col.f32.tf32.tf32.f32 "
        "{%0,%1,%2,%3}, {%4,%5,%6,%7}, {%8,%9}, {%0,%1,%2,%3};"
        : "+f"(d[0]), "+f"(d[1]), "+f"(d[2]), "+f"(d[3])
        : "r"(a0), "r"(a1), "r"(a2), "r"(a3), "r"(b0), "r"(b1));
}

// ---------------- scheduler ----------------
__global__ void sched_kernel(const int* __restrict__ bs) {
    if (threadIdx.x == 0) {
        int off = 0, nt = 0;
        for (int e = 0; e < E_EXPERTS; e++) {
            int b = bs[e];
            for (int r = 0; r < b; r += TILE_M) {
                g_te[nt] = e; g_tr0[nt] = off + r; g_tlim[nt] = off + b; nt++;
            }
            off += b;
        }
        g_ntiles = nt;
    }
}

// ---------------- chunk issue: gmem -> smem via cp.async ----------------
// A: 128 rows x 128B (8x 16B per row), 1024 copies / 128 thr = 8 each, coalesced.
// B: 32 k-rows x 512B (32x 16B per row), 1024 copies / 128 thr = 8 each, coalesced.
__device__ __forceinline__ void issue_chunk(int c, uint32_t stA, uint32_t stB,
        const float* __restrict__ x, const float* __restrict__ wb,
        int r0, int tid) {
#pragma unroll
    for (int j = 0; j < 8; j++) {
        int task = j * 128 + tid;
        int m = task >> 3, f = task & 7;
        int gr = r0 + m;
        int ok = gr < S_TOK;
        int grc = ok ? gr : (S_TOK - 1);
        cp16(stA + (uint32_t)(m * (A_STRIDE * 4) + f * 16),
             x + (size_t)grc * MFEAT + c * KC + f * 4, ok);
    }
#pragma unroll
    for (int j = 0; j < 8; j++) {
        int task = j * 128 + tid;
        int k = task >> 5, t = task & 31;
        cp16(stB + (uint32_t)(k * (B_STRIDE * 4) + t * 16),
             wb + (size_t)(c * KC + k) * NFEAT + t * 4, 1);
    }
}

// ---------------- main grouped-GEMM kernel ----------------
// 128 threads, 4 warps (2x2), warp tile 64x64, 3-stage cp.async pipeline.
__global__ __launch_bounds__(128, 2)
void gg_kernel(const float* __restrict__ x, const float* __restrict__ w, float* __restrict__ out) {
    int job = blockIdx.x;
    int tm = job / NTN;
    if (tm >= g_ntiles) return;
    int n0   = (job - tm * NTN) * TILE_N;
    int e    = g_te[tm];
    int r0   = g_tr0[tm];
    int rlim = g_tlim[tm];
    const float* wb = w + (size_t)e * ((size_t)MFEAT * NFEAT) + n0;

    extern __shared__ __align__(16) float smem[];
    uint32_t smem_b = smem_u32(smem);

    int tid  = threadIdx.x;
    int lane = tid & 31;
    int wid  = tid >> 5;
    int m0w  = (wid & 1) * 64;
    int n0w  = (wid >> 1) * 64;

    int lr = lane >> 2;          // 0..7
    int lc = lane & 3;           // 0..3
    // ldmatrix lane->row mapping: tiles 0..3 from lane groups 0-7/8-15/16-23/24-31
    int lsub = lane >> 3;
    int r8   = lane & 7;
    int mrow = (lsub & 1) * 8 + r8;     // row within 16-row frag
    int kh   = (lsub >> 1) * 4;         // k-half offset (0 or 4)

    float acc[4][8][4];
#pragma unroll
    for (int i = 0; i < 4; i++)
#pragma unroll
        for (int j = 0; j < 8; j++)
#pragma unroll
            for (int q = 0; q < 4; q++) acc[i][j][q] = 0.f;

    // prologue: fill 3 stages
#pragma unroll
    for (int s = 0; s < STAGES; s++) {
        uint32_t st = smem_b + (uint32_t)s * STAGE_BYTES;
        issue_chunk(s, st, st + A_FLOATS * 4, x, wb, r0, tid);
        CP_COMMIT();
    }

    int stage = 0;
    for (int c = 0; c < NCHUNK; c++) {
        CP_WAIT2();              // oldest of 3 pending groups (chunk c) complete
        __syncthreads();

        uint32_t stA = smem_b + (uint32_t)stage * STAGE_BYTES;
        const float* Bs = smem + (size_t)stage * STAGE_FLOATS + A_FLOATS;
        // per-lane ldmatrix base for this stage/warp
        uint32_t aBase = stA + (uint32_t)((m0w + mrow) * (A_STRIDE * 4) + kh * 4);

#pragma unroll
        for (int s = 0; s < 4; s++) {   // 4 k-steps of 8
            uint32_t af[4][4];
#pragma unroll
            for (int mf = 0; mf < 4; mf++)
                ldsm_x4(af[mf][0], af[mf][1], af[mf][2], af[mf][3],
                        aBase + (uint32_t)(mf * 16 * (A_STRIDE * 4) + s * 32));
            uint32_t bf[8][2];
            const float* bp0 = Bs + (size_t)(s * 8 + lc) * B_STRIDE + n0w + lr;
#pragma unroll
            for (int nf = 0; nf < 8; nf++) {
                bf[nf][0] = __float_as_uint(bp0[nf * 8]);
                bf[nf][1] = __float_as_uint(bp0[4 * B_STRIDE + nf * 8]);
            }
#pragma unroll
            for (int mf = 0; mf < 4; mf++)
#pragma unroll
                for (int nf = 0; nf < 8; nf++)
                    mma_m16n8k8(acc[mf][nf],
                                af[mf][0], af[mf][1], af[mf][2], af[mf][3],
                                bf[nf][0], bf[nf][1]);
        }

        __syncthreads();          // all warps done reading this stage
        int cn = c + STAGES;
        if (cn < NCHUNK) {
            uint32_t st = smem_b + (uint32_t)stage * STAGE_BYTES;
            issue_chunk(cn, st, st + A_FLOATS * 4, x, wb, r0, tid);
        }
        CP_COMMIT();              // commit (possibly empty) keeps group accounting fixed
        stage = (stage + 1 == STAGES) ? 0 : stage + 1;
    }

    // ---------------- epilogue ----------------
#pragma unroll
    for (int mf = 0; mf < 4; mf++) {
        int r_lo = r0 + m0w + mf * 16 + lr;
#pragma unroll
        for (int h = 0; h < 2; h++) {
            int gr = r_lo + h * 8;
            if (gr < rlim) {
                float* orow = out + (size_t)gr * NFEAT + n0 + n0w + 2 * lc;
#pragma unroll
                for (int nf = 0; nf < 8; nf++) {
                    float2 v;
                    v.x = acc[mf][nf][h * 2 + 0];
                    v.y = acc[mf][nf][h * 2 + 1];
                    *(float2*)(orow + nf * 8) = v;
                }
            }
        }
    }
}

// ---------------- launch ----------------
extern "C" void kernel_launch(void* const* d_in, const int* in_sizes, int n_in,
                              void* d_out, int out_size) {
    const float* x  = (const float*)d_in[0];
    const float* w  = (const float*)d_in[1];
    const int*   bs = (const int*)d_in[2];
    float* out = (float*)d_out;

    cudaFuncSetAttribute(gg_kernel, cudaFuncAttributeMaxDynamicSharedMemorySize, SMEM_DYN);
    sched_kernel<<<1, 32>>>(bs);
    gg_kernel<<<GRID_CTAS, 128, SMEM_DYN>>>(x, w, out);
}